// round 16
// baseline (speedup 1.0000x reference)
#include <cuda_runtime.h>
#include <cuda_fp16.h>

// ---------------------------------------------------------------------------
// CustomGraphConv on GB300 — R16: smem-W precompute (1 node/thread, 21
// warps/SM) + frozen R15 edge/finalize.
//
//   msg[e,o]  = sum_{a,i} edge_attr[e,a] * W[a,o,i] * x[src_e, i]
//   aggr[n,o] = segment_sum over dst ; out = relu(aggr + bias)
//
// R15 profile: precompute occ=8.6% (782 warps chip-wide, 4 nodes/thread) ->
// 20us of exposed latency over the ~12us FFMA floor. Staging W in smem
// amortizes W per BLOCK, so 1 node/thread (3125 warps) costs no extra
// global W traffic. All W reads are warp-uniform LDS -> broadcast,
// conflict-free (R2's conflict came from per-lane different rows).
// ---------------------------------------------------------------------------

#define MAX_NODES 100000

// layout: [n][c=16][a=8] fp16, chunk c holds o = (c<8) ? 2c : 2(c-8)+1
__device__ __half g_yh[MAX_NODES * 128];      // 25.6 MB (L2-resident)
__device__ float  g_accum[MAX_NODES * 16];    // 6.4 MB, zero at load; each
                                              // call restores it to zero.

// ---------------------------------------------------------------------------
// P1: y[n][c(o)][a] = dot(W[a][o][:], x[n][:]). One node per thread.
// W staged in smem (8KB) once per block; inner reads are warp-uniform
// LDS.128 broadcasts. Per thread: 4 x-LDG.128, 512 LDS.128, 2048 FFMA,
// 16 STG.128.
// ---------------------------------------------------------------------------
__global__ void __launch_bounds__(256)
precompute_y_kernel(const float* __restrict__ x,
                    const float* __restrict__ W,
                    int N) {
    __shared__ float4 Ws[512];          // [row=(a*16+o)][q=0..3]
    for (int i = threadIdx.x; i < 512; i += blockDim.x)
        Ws[i] = ((const float4*)W)[i];
    __syncthreads();

    int n = blockIdx.x * blockDim.x + threadIdx.x;
    if (n >= N) return;

    const float4* x4 = (const float4*)x + (long long)n * 4;
    float4 x0 = x4[0], x1 = x4[1], x2 = x4[2], x3 = x4[3];

    uint4* yp = (uint4*)g_yh + (long long)n * 16;

#pragma unroll 2
    for (int o = 0; o < 16; ++o) {
        float acc[8];
#pragma unroll
        for (int a = 0; a < 8; ++a) {
            int row = a * 16 + o;
            float4 w0 = Ws[row * 4 + 0];   // warp-uniform -> LDS broadcast
            float4 w1 = Ws[row * 4 + 1];
            float4 w2 = Ws[row * 4 + 2];
            float4 w3 = Ws[row * 4 + 3];
            float v;
            v  = w0.x * x0.x + w0.y * x0.y + w0.z * x0.z + w0.w * x0.w;
            v += w1.x * x1.x + w1.y * x1.y + w1.z * x1.z + w1.w * x1.w;
            v += w2.x * x2.x + w2.y * x2.y + w2.z * x2.z + w2.w * x2.w;
            v += w3.x * x3.x + w3.y * x3.y + w3.z * x3.z + w3.w * x3.w;
            acc[a] = v;
        }
        // parity-permuted chunk: even o -> chunks 0..7, odd o -> chunks 8..15
        int c = (o & 1) * 8 + (o >> 1);
        __half2 h0 = __floats2half2_rn(acc[0], acc[1]);
        __half2 h1 = __floats2half2_rn(acc[2], acc[3]);
        __half2 h2 = __floats2half2_rn(acc[4], acc[5]);
        __half2 h3 = __floats2half2_rn(acc[6], acc[7]);
        uint4 u;
        u.x = *(unsigned*)&h0;
        u.y = *(unsigned*)&h1;
        u.z = *(unsigned*)&h2;
        u.w = *(unsigned*)&h3;
        yp[c] = u;
    }
}

// ---------------------------------------------------------------------------
// P2 (frozen from R15): 8 lanes/edge, 8 edges/warp.
// Lane s loads chunks {s, s+8}: one 128B line each (2 wavefronts/edge).
// Chunk s = o=2s (all 8 a-values); chunk s+8 = o=2s+1. Register dot with
// ea[e][0..8]. ZERO shfl. ONE red.global.add.v2.f32 per lane at
// g_accum[dst][2s] (the 8 lanes' reds form one contiguous 64B burst).
// ---------------------------------------------------------------------------
__global__ void edge_scatter_kernel(const int* __restrict__ ei,
                                    const float* __restrict__ eattr,
                                    int E) {
    int lane = threadIdx.x & 31;
    int warp = (blockIdx.x * blockDim.x + threadIdx.x) >> 5;
    int g = lane >> 3;   // edge slot within warp (0..3)
    int s = lane & 7;    // sublane within edge

#pragma unroll
    for (int t = 0; t < 2; ++t) {
        int e = warp * 8 + t * 4 + g;
        if (e >= E) break;  // uniform across the 8-lane group

        int src = ei[e];
        const uint4* yv = (const uint4*)g_yh + (long long)src * 16;
        const float4* ea4 = (const float4*)(eattr + (long long)e * 8);
        float4 ea0 = ea4[0];
        float4 ea1 = ea4[1];

        uint4 v0 = yv[s];        // o = 2s    (lanes 0..7 -> line 0)
        uint4 v1 = yv[s + 8];    // o = 2s+1  (lanes 0..7 -> line 1)

        float m0, m1;
        {
            const __half2* h = (const __half2*)&v0;
            float2 f0 = __half22float2(h[0]);
            float2 f1 = __half22float2(h[1]);
            float2 f2 = __half22float2(h[2]);
            float2 f3 = __half22float2(h[3]);
            m0 = f0.x * ea0.x + f0.y * ea0.y + f1.x * ea0.z + f1.y * ea0.w
               + f2.x * ea1.x + f2.y * ea1.y + f3.x * ea1.z + f3.y * ea1.w;
        }
        {
            const __half2* h = (const __half2*)&v1;
            float2 f0 = __half22float2(h[0]);
            float2 f1 = __half22float2(h[1]);
            float2 f2 = __half22float2(h[2]);
            float2 f3 = __half22float2(h[3]);
            m1 = f0.x * ea0.x + f0.y * ea0.y + f1.x * ea0.z + f1.y * ea0.w
               + f2.x * ea1.x + f2.y * ea1.y + f3.x * ea1.z + f3.y * ea1.w;
        }

        int dst = ei[E + e];
        float* p = g_accum + (long long)dst * 16 + 2 * s;
        asm volatile("red.global.add.v2.f32 [%0], {%1, %2};"
                     :: "l"(p), "f"(m0), "f"(m1) : "memory");
    }
}

// ---------------------------------------------------------------------------
// P3 (frozen from R15): out = relu(accum + bias); accum = 0 (restores the
// zero invariant for the next call / graph replay).
// ---------------------------------------------------------------------------
__global__ void finalize_kernel(float4* __restrict__ out,
                                const float* __restrict__ bias,
                                int total4) {
    int i = blockIdx.x * blockDim.x + threadIdx.x;
    if (i >= total4) return;
    float4 v = ((float4*)g_accum)[i];
    float4 b = ((const float4*)bias)[i & 3];
    v.x = fmaxf(v.x + b.x, 0.f);
    v.y = fmaxf(v.y + b.y, 0.f);
    v.z = fmaxf(v.z + b.z, 0.f);
    v.w = fmaxf(v.w + b.w, 0.f);
    out[i] = v;
    ((float4*)g_accum)[i] = make_float4(0.f, 0.f, 0.f, 0.f);
}

// ---------------------------------------------------------------------------
// inputs (metadata order): x[N,16] f32, edge_index[2,E] i32, edge_attr[E,8]
//   f32, weight_matrix[8,16,16] f32, bias[16] f32, num_nodes
// output: [N,16] f32
//
// Launch order: 1 precompute  2 edge  3 finalize
// ---------------------------------------------------------------------------
extern "C" void kernel_launch(void* const* d_in, const int* in_sizes, int n_in,
                              void* d_out, int out_size) {
    const float* x = (const float*)d_in[0];
    const int* ei = (const int*)d_in[1];
    const float* eattr = (const float*)d_in[2];
    const float* W = (const float*)d_in[3];
    const float* bias = (const float*)d_in[4];

    int N = in_sizes[0] / 16;
    int E = in_sizes[2] / 8;
    float* out = (float*)d_out;

    // 1: per-node precompute (1 node/thread, W in smem)
    precompute_y_kernel<<<(N + 255) / 256, 256>>>(x, W, N);
    // 2: edge gather/scatter into g_accum
    {
        long long warps = ((long long)E + 7) / 8;
        long long threads = warps * 32;
        int blocks = (int)((threads + 255) / 256);
        edge_scatter_kernel<<<blocks, 256>>>(ei, eattr, E);
    }
    // 3: finalize: out = relu(accum + bias), accum -> 0
    {
        int total4 = out_size / 4;
        finalize_kernel<<<(total4 + 255) / 256, 256>>>((float4*)out, bias, total4);
    }
}

// round 17
// speedup vs baseline: 1.3823x; 1.3823x over previous
#include <cuda_runtime.h>
#include <cuda_fp16.h>

// ---------------------------------------------------------------------------
// CustomGraphConv on GB300 — R17: o-stationary persistent precompute
// (W register-resident, zero W traffic in steady state) + frozen R15
// edge/finalize.
//
//   msg[e,o]  = sum_{a,i} edge_attr[e,a] * W[a,o,i] * x[src_e, i]
//   aggr[n,o] = segment_sum over dst ; out = relu(aggr + bias)
//
// Post-R16 invariant: chip FFMA fixed at 6.4M warp-inst (~12us floor); all
// precompute variants differ only in extra MIO ops + latency coverage.
// W-in-registers (one o per lane, 128 W floats) removes the per-node
// 512-load stream entirely. Persistent grid = 296 blocks (exactly 2/SM,
// no tail imbalance), 1184 warps loop over node pairs.
// ---------------------------------------------------------------------------

#define MAX_NODES 100000

// layout: [n][c=16][a=8] fp16, chunk c holds o = (c<8) ? 2c : 2(c-8)+1
__device__ __half g_yh[MAX_NODES * 128];      // 25.6 MB (L2-resident)
__device__ float  g_accum[MAX_NODES * 16];    // 6.4 MB, zero at load; each
                                              // call restores it to zero.

// ---------------------------------------------------------------------------
// P1: y[n][c(o)][a] = dot(W[a][o][:], x[n][:]).
// Warp layout: lane = o*2 + npar  (16 output channels x 2 nodes per iter).
// Each lane keeps W[a][o][:] for all a in 32 float4 registers (full unroll,
// loaded once per persistent warp). Steady-state loop per node pair:
// 4 x-LDG.128 (2 distinct rows -> 2 wf each), 128 warp-FFMA (= 64/node,
// the floor), 1 STG.128 per lane (2 nodes x 256B contiguous = 4 wf).
// ---------------------------------------------------------------------------
__global__ void __launch_bounds__(128)
precompute_y_kernel(const float* __restrict__ x,
                    const float* __restrict__ W,
                    int N) {
    int lane = threadIdx.x & 31;
    int warp_global = (blockIdx.x * blockDim.x + threadIdx.x) >> 5;
    int total_warps = gridDim.x * (blockDim.x >> 5);

    int o = lane >> 1;              // output channel owned by this lane
    int npar = lane & 1;            // which node of the pair
    int c = (o & 1) * 8 + (o >> 1); // parity-permuted chunk index

    // W rows for this o, all a: 128 floats in registers.
    float4 Wreg[8][4];
#pragma unroll
    for (int a = 0; a < 8; ++a) {
#pragma unroll
        for (int q = 0; q < 4; ++q)
            Wreg[a][q] = ((const float4*)W)[(a * 16 + o) * 4 + q];
    }

    int npairs = (N + 1) >> 1;
    for (int p = warp_global; p < npairs; p += total_warps) {
        int n = p * 2 + npar;
        if (n >= N) n = N - 1;      // duplicate write of same data: benign

        const float4* xp = (const float4*)x + (long long)n * 4;
        float4 x0 = xp[0], x1 = xp[1], x2 = xp[2], x3 = xp[3];

        float acc[8];
#pragma unroll
        for (int a = 0; a < 8; ++a) {
            float v;
            v  = Wreg[a][0].x * x0.x + Wreg[a][0].y * x0.y
               + Wreg[a][0].z * x0.z + Wreg[a][0].w * x0.w;
            v += Wreg[a][1].x * x1.x + Wreg[a][1].y * x1.y
               + Wreg[a][1].z * x1.z + Wreg[a][1].w * x1.w;
            v += Wreg[a][2].x * x2.x + Wreg[a][2].y * x2.y
               + Wreg[a][2].z * x2.z + Wreg[a][2].w * x2.w;
            v += Wreg[a][3].x * x3.x + Wreg[a][3].y * x3.y
               + Wreg[a][3].z * x3.z + Wreg[a][3].w * x3.w;
            acc[a] = v;
        }

        __half2 h0 = __floats2half2_rn(acc[0], acc[1]);
        __half2 h1 = __floats2half2_rn(acc[2], acc[3]);
        __half2 h2 = __floats2half2_rn(acc[4], acc[5]);
        __half2 h3 = __floats2half2_rn(acc[6], acc[7]);
        uint4 u;
        u.x = *(unsigned*)&h0;
        u.y = *(unsigned*)&h1;
        u.z = *(unsigned*)&h2;
        u.w = *(unsigned*)&h3;
        ((uint4*)g_yh)[(long long)n * 16 + c] = u;
    }
}

// ---------------------------------------------------------------------------
// P2 (frozen from R15): 8 lanes/edge, 8 edges/warp.
// Lane s loads chunks {s, s+8}: one 128B line each (2 wavefronts/edge).
// Chunk s = o=2s (all 8 a-values); chunk s+8 = o=2s+1. Register dot with
// ea[e][0..8]. ZERO shfl. ONE red.global.add.v2.f32 per lane at
// g_accum[dst][2s] (the 8 lanes' reds form one contiguous 64B burst).
// ---------------------------------------------------------------------------
__global__ void edge_scatter_kernel(const int* __restrict__ ei,
                                    const float* __restrict__ eattr,
                                    int E) {
    int lane = threadIdx.x & 31;
    int warp = (blockIdx.x * blockDim.x + threadIdx.x) >> 5;
    int g = lane >> 3;   // edge slot within warp (0..3)
    int s = lane & 7;    // sublane within edge

#pragma unroll
    for (int t = 0; t < 2; ++t) {
        int e = warp * 8 + t * 4 + g;
        if (e >= E) break;  // uniform across the 8-lane group

        int src = ei[e];
        const uint4* yv = (const uint4*)g_yh + (long long)src * 16;
        const float4* ea4 = (const float4*)(eattr + (long long)e * 8);
        float4 ea0 = ea4[0];
        float4 ea1 = ea4[1];

        uint4 v0 = yv[s];        // o = 2s    (lanes 0..7 -> line 0)
        uint4 v1 = yv[s + 8];    // o = 2s+1  (lanes 0..7 -> line 1)

        float m0, m1;
        {
            const __half2* h = (const __half2*)&v0;
            float2 f0 = __half22float2(h[0]);
            float2 f1 = __half22float2(h[1]);
            float2 f2 = __half22float2(h[2]);
            float2 f3 = __half22float2(h[3]);
            m0 = f0.x * ea0.x + f0.y * ea0.y + f1.x * ea0.z + f1.y * ea0.w
               + f2.x * ea1.x + f2.y * ea1.y + f3.x * ea1.z + f3.y * ea1.w;
        }
        {
            const __half2* h = (const __half2*)&v1;
            float2 f0 = __half22float2(h[0]);
            float2 f1 = __half22float2(h[1]);
            float2 f2 = __half22float2(h[2]);
            float2 f3 = __half22float2(h[3]);
            m1 = f0.x * ea0.x + f0.y * ea0.y + f1.x * ea0.z + f1.y * ea0.w
               + f2.x * ea1.x + f2.y * ea1.y + f3.x * ea1.z + f3.y * ea1.w;
        }

        int dst = ei[E + e];
        float* p = g_accum + (long long)dst * 16 + 2 * s;
        asm volatile("red.global.add.v2.f32 [%0], {%1, %2};"
                     :: "l"(p), "f"(m0), "f"(m1) : "memory");
    }
}

// ---------------------------------------------------------------------------
// P3 (frozen from R15): out = relu(accum + bias); accum = 0 (restores the
// zero invariant for the next call / graph replay).
// ---------------------------------------------------------------------------
__global__ void finalize_kernel(float4* __restrict__ out,
                                const float* __restrict__ bias,
                                int total4) {
    int i = blockIdx.x * blockDim.x + threadIdx.x;
    if (i >= total4) return;
    float4 v = ((float4*)g_accum)[i];
    float4 b = ((const float4*)bias)[i & 3];
    v.x = fmaxf(v.x + b.x, 0.f);
    v.y = fmaxf(v.y + b.y, 0.f);
    v.z = fmaxf(v.z + b.z, 0.f);
    v.w = fmaxf(v.w + b.w, 0.f);
    out[i] = v;
    ((float4*)g_accum)[i] = make_float4(0.f, 0.f, 0.f, 0.f);
}

// ---------------------------------------------------------------------------
// inputs (metadata order): x[N,16] f32, edge_index[2,E] i32, edge_attr[E,8]
//   f32, weight_matrix[8,16,16] f32, bias[16] f32, num_nodes
// output: [N,16] f32
//
// Launch order: 1 precompute  2 edge  3 finalize
// ---------------------------------------------------------------------------
extern "C" void kernel_launch(void* const* d_in, const int* in_sizes, int n_in,
                              void* d_out, int out_size) {
    const float* x = (const float*)d_in[0];
    const int* ei = (const int*)d_in[1];
    const float* eattr = (const float*)d_in[2];
    const float* W = (const float*)d_in[3];
    const float* bias = (const float*)d_in[4];

    int N = in_sizes[0] / 16;
    int E = in_sizes[2] / 8;
    float* out = (float*)d_out;

    // 1: per-node precompute (persistent, o-stationary, W in registers)
    //    grid = 296 blocks x 128 threads = exactly 2 blocks/SM on 148 SMs
    precompute_y_kernel<<<296, 128>>>(x, W, N);
    // 2: edge gather/scatter into g_accum
    {
        long long warps = ((long long)E + 7) / 8;
        long long threads = warps * 32;
        int blocks = (int)((threads + 255) / 256);
        edge_scatter_kernel<<<blocks, 256>>>(ei, eattr, E);
    }
    // 3: finalize: out = relu(accum + bias), accum -> 0
    {
        int total4 = out_size / 4;
        finalize_kernel<<<(total4 + 255) / 256, 256>>>((float4*)out, bias, total4);
    }
}